// round 17
// baseline (speedup 1.0000x reference)
#include <cuda_runtime.h>
#include <cstdint>

// RecurrentCharLM: B=256, S=32, H=128, VOCAB=256, DEPTH=100, L=1.
// R11/R15 architecture (best): 128 blocks x 256 threads, 2 rows/block,
// thread = (row, col-quad p, k-quarter s2), W 4 cols x 32 k in 128 regs,
// row-scoped named barriers, row1 dephased, 8x LDS.128 batch.
// NEW vs R15:
//  * XOR-permuted W ownership (slot i tracks column c0 + (s2 ^ i)) makes the
//    reduce-scatter select-free: h1 = fA + shfl8(fB); h2 = fC + shfl8(fD);
//    h = relu(h1 + shfl16(h2)). No SELs, shorter dependent tail.
//  * chars/embed for timestep t+1 prefetched at t's start (two dependent
//    LDGs hidden under the 100 iterations).

#define BATCH 256
#define SEQ   32
#define HID   128
#define VOC   256
#define DEPTH_IT 100
#define NBLK  128
#define NTHR  256
#define QP    144          // byte pitch between 32-col segments of h
#define HROW  (4*QP)       // 576 bytes per row buffer

typedef unsigned long long ull;

__device__ __forceinline__ ull pack2(float lo, float hi) {
    ull r; asm("mov.b64 %0, {%1,%2};" : "=l"(r) : "f"(lo), "f"(hi)); return r;
}
__device__ __forceinline__ void unpack2(ull v, float &lo, float &hi) {
    asm("mov.b64 {%0,%1}, %2;" : "=f"(lo), "=f"(hi) : "l"(v));
}
__device__ __forceinline__ ull fma2(ull a, ull b, ull c) {
    ull d; asm("fma.rn.f32x2 %0, %1, %2, %3;" : "=l"(d) : "l"(a), "l"(b), "l"(c));
    return d;
}
__device__ __forceinline__ ull add2(ull a, ull b) {
    ull d; asm("add.rn.f32x2 %0, %1, %2;" : "=l"(d) : "l"(a), "l"(b)); return d;
}
__device__ __forceinline__ ull d2u(double x) { return __double_as_longlong(x); }
__device__ __forceinline__ void row_bar(int id) {
    asm volatile("bar.sync %0, 128;" :: "r"(id) : "memory");
}
__device__ __forceinline__ float red1(ull s) {   // f32x2 -> scalar
    float lo, hi; unpack2(s, lo, hi); return lo + hi;
}

// One recurrence iteration. Slot roles are lane-uniform thanks to the
// XOR-permuted W load: slot i of this lane accumulates column c0 + (s2^i).
//   h1 = fA + shfl8(fB)   -> tracked col over quarters {s2, s2^1}
//   h2 = fC + shfl8(fD)   -> col c0+(s2^2) over quarters {s2, s2^1}
//   h  = relu(h1 + shfl16(h2))  -> full sum of owned col c0+s2
__device__ __forceinline__ float iter_once(
    const char* __restrict__ src, char* __restrict__ dst,
    int s2, int ooff, int bid,
    const ull* __restrict__ wA, const ull* __restrict__ wB,
    const ull* __restrict__ wC, const ull* __restrict__ wD)
{
    const double2* pa = (const double2*)(src + s2 * QP);
    double2 x[8];
#pragma unroll
    for (int q = 0; q < 8; ++q) x[q] = pa[q];          // batched LDS (MLP)

    // ---- FMA block 1: slots A, B
    ull aE = 0, aO = 0, bE = 0, bO = 0;
#pragma unroll
    for (int q = 0; q < 8; ++q) {
        aE = fma2(d2u(x[q].x), wA[2 * q],     aE);
        bE = fma2(d2u(x[q].x), wB[2 * q],     bE);
        aO = fma2(d2u(x[q].y), wA[2 * q + 1], aO);
        bO = fma2(d2u(x[q].y), wB[2 * q + 1], bO);
    }
    float fA = red1(add2(aE, aO));
    float fB = red1(add2(bE, bO));
    float rB = __shfl_xor_sync(0xffffffffu, fB, 8);    // drains under block 2

    // ---- FMA block 2: slots C, D
    ull cE = 0, cO = 0, dE = 0, dO = 0;
#pragma unroll
    for (int q = 0; q < 8; ++q) {
        cE = fma2(d2u(x[q].x), wC[2 * q],     cE);
        dE = fma2(d2u(x[q].x), wD[2 * q],     dE);
        cO = fma2(d2u(x[q].y), wC[2 * q + 1], cO);
        dO = fma2(d2u(x[q].y), wD[2 * q + 1], dO);
    }
    float fC = red1(add2(cE, cO));
    float fD = red1(add2(dE, dO));
    float rD = __shfl_xor_sync(0xffffffffu, fD, 8);

    float h1 = fA + rB;
    float h2 = fC + rD;
    float r2 = __shfl_xor_sync(0xffffffffu, h2, 16);
    float h = fmaxf(h1 + r2, 0.0f);

    *(float*)(dst + ooff) = h;
    row_bar(bid);
    return h;
}

__global__ void __launch_bounds__(NTHR, 1)
rnn_charlm_kernel(const int* __restrict__ chars,
                  const float* __restrict__ hidden,
                  const float* __restrict__ embed_w,
                  const float* __restrict__ Wg,      // (1,128,128): W[k][j]
                  const float* __restrict__ ro_w,    // (256,128)
                  const float* __restrict__ ro_b,    // (256,)
                  float* __restrict__ out, int out_size)
{
    // dynamic smem: ro_w in k-paired transposed layout
    // ro_p[(k>>1)*512 + 2*v + (k&1)] = ro_w[v][k]   (64*512 floats = 128KB)
    extern __shared__ float ro_p[];
    __shared__ __align__(16) char hsraw[2][2][HROW];   // [buf][row][bytes]

    const int tid = threadIdx.x;
    const int row = tid >> 7;               // 0 or 1
    const int w   = (tid >> 5) & 3;         // warp within row
    const int l   = tid & 31;               // lane
    const int s2  = l >> 3;                 // k-quarter 0..3
    const int p   = w * 8 + (l & 7);        // col-quad index 0..31
    const int c0  = 4 * p;                  // first of 4 columns
    const int R   = blockIdx.x * 2 + row;   // global batch row
    const int j   = w * 32 + l;             // readout col id 0..127
    const int ks  = s2 * 32;                // my k-range start
    const int bid = 1 + row;                // named barrier id
    const int colown = c0 + s2;             // owned column (slot A)

    // ---- W, XOR-permuted: slot i holds column c0 + (s2 ^ i), k-packed
    const int cA = c0 + s2;
    const int cB = c0 + (s2 ^ 1);
    const int cC = c0 + (s2 ^ 2);
    const int cD = c0 + (s2 ^ 3);
    ull wA[16], wB[16], wC[16], wD[16];
#pragma unroll
    for (int i = 0; i < 16; ++i) {
        const float* r0 = &Wg[(ks + 2 * i) * HID];
        const float* r1 = &Wg[(ks + 2 * i + 1) * HID];
        wA[i] = pack2(r0[cA], r1[cA]);
        wB[i] = pack2(r0[cB], r1[cB]);
        wC[i] = pack2(r0[cC], r1[cC]);
        wD[i] = pack2(r0[cD], r1[cD]);
    }

    // ---- stage ro_w into smem (once)
    for (int idx = tid; idx < VOC * HID; idx += NTHR) {
        int v = idx / HID, k = idx % HID;
        ro_p[(k >> 1) * 512 + 2 * v + (k & 1)] = ro_w[idx];
    }

    float hval = hidden[R * HID + colown];       // this lane's owned column
    const float rb_lo = ro_b[j];
    const float rb_hi = ro_b[j + 128];
    __syncthreads();   // ro_p staged

    // ---- SYMMETRY BREAKER: row1 delayed ~240 cyc (exact-identity chain)
    if (row == 1) {
        const float one = __int_as_float(0x3f800000);
        float d = hval;
#pragma unroll
        for (int i = 0; i < 60; ++i)
            asm volatile("mul.f32 %0, %0, %1;" : "+f"(d) : "f"(one));
        hval = d;
    }

    // smem byte address (within a row buffer) of this lane's owned column
    const int ooff = (colown >> 5) * QP + (colown & 31) * 4;

    // preload embed for t=0
    float e_cur = embed_w[chars[R * SEQ] * HID + colown];

    int cur = 0;
    for (int t = 0; t < SEQ; ++t) {
        // prefetch t+1's embed (two dependent LDGs, covered by the 100 iters)
        const int  c_next = (t + 1 < SEQ) ? chars[R * SEQ + t + 1] : 0;
        const float e_next = embed_w[c_next * HID + colown];

        // embed add on the owned column; publish into next buffer
        hval += e_cur;
        cur ^= 1;
        char* bufA = hsraw[cur][row];
        char* bufB = hsraw[cur ^ 1][row];
        *(float*)(bufA + ooff) = hval;
        row_bar(bid);

        // ---- 100 chained relu(h @ W) iterations, unrolled x2 (static bufs)
        for (int it = 0; it < DEPTH_IT / 2; ++it) {
            hval = iter_once(bufA, bufB, s2, ooff, bid, wA, wB, wC, wD);
            hval = iter_once(bufB, bufA, s2, ooff, bid, wA, wB, wC, wD);
        }
        // after an even number of iterations h is in bufA

        // ---- readout: logits[R][v] for v = j and v = j+128
        {
            const char* hb = bufA;
            ull A0a = 0, A0b = 0, A1a = 0, A1b = 0;
#pragma unroll
            for (int q = 0; q < 32; ++q) {       // quad q covers k = 4q..4q+3
                double2 x = *(const double2*)(hb + (q >> 3) * QP + (q & 7) * 16);
                const float* b0 = &ro_p[(2 * q) * 512];
                const float* b1 = &ro_p[(2 * q + 1) * 512];
                ull ra0 = *(const ull*)&b0[2 * j];
                ull rc0 = *(const ull*)&b0[256 + 2 * j];
                ull ra1 = *(const ull*)&b1[2 * j];
                ull rc1 = *(const ull*)&b1[256 + 2 * j];
                A0a = fma2(d2u(x.x), ra0, A0a);
                A1a = fma2(d2u(x.x), rc0, A1a);
                A0b = fma2(d2u(x.y), ra1, A0b);
                A1b = fma2(d2u(x.y), rc1, A1b);
            }
            float lo, hi;
            float* o = out + (R * SEQ + t) * VOC;
            ull A0 = add2(A0a, A0b);
            ull A1 = add2(A1a, A1b);
            unpack2(A0, lo, hi); o[j]       = lo + hi + rb_lo;
            unpack2(A1, lo, hi); o[j + 128] = lo + hi + rb_hi;
        }
        e_cur = e_next;
        // next timestep's embed-store targets the OTHER buffer; its row barrier
        // orders subsequent in-loop writes against these readout reads.
    }

    // ---- h_final (if the harness output includes it after the logits)
    if (out_size >= BATCH * SEQ * VOC + BATCH * HID) {
        float* hf = out + BATCH * SEQ * VOC;
        hf[R * HID + colown] = hval;
    }
}

extern "C" void kernel_launch(void* const* d_in, const int* in_sizes, int n_in,
                              void* d_out, int out_size)
{
    (void)in_sizes; (void)n_in;
    const int*   chars   = (const int*)d_in[0];
    const float* hidden  = (const float*)d_in[1];
    const float* embed_w = (const float*)d_in[2];
    const float* Ws      = (const float*)d_in[3];
    const float* ro_w    = (const float*)d_in[4];
    const float* ro_b    = (const float*)d_in[5];
    float* out = (float*)d_out;

    const size_t smem = 64 * 512 * sizeof(float);   // 128KB dynamic
    cudaFuncSetAttribute(rnn_charlm_kernel,
                         cudaFuncAttributeMaxDynamicSharedMemorySize, (int)smem);
    rnn_charlm_kernel<<<NBLK, NTHR, smem>>>(chars, hidden, embed_w, Ws,
                                            ro_w, ro_b, out, out_size);
}